// round 5
// baseline (speedup 1.0000x reference)
#include <cuda_runtime.h>

#define W_IMG 3840
#define H_IMG 2160
#define TILE_W 30            // output columns per strip (lanes 1..30)
#define STRIP_H 30           // output rows per strip
#define NW_X 128             // 3840 / 30
#define NW_Y 72              // 2160 / 30
#define NSTRIPS (NW_X * NW_Y)            // 9216
#define WPB 8
#define NTHREADS 256
#define NBLOCKS 592                       // 148 SMs x 4 resident blocks
#define NSLOTS (NBLOCKS * WPB)            // 4736 warp slots

__device__ double g_num;
__device__ unsigned int g_cnt;
__device__ unsigned int g_ticket;

__launch_bounds__(NTHREADS, 4)
__global__ void shading_loss_kernel(const float* __restrict__ depth,
                                    const float* __restrict__ rgb,
                                    const int*   __restrict__ mask,
                                    const float* __restrict__ l,
                                    const float* __restrict__ Kc,
                                    float* __restrict__ out)
{
    const int tid  = threadIdx.x;
    const int lane = tid & 31;
    const int w    = tid >> 5;
    const int slot = blockIdx.x * WPB + w;

    // camera inverse (adjugate) — uniform
    float a = Kc[0], b = Kc[1], cc = Kc[2];
    float d = Kc[3], e = Kc[4], f  = Kc[5];
    float g = Kc[6], h = Kc[7], i  = Kc[8];
    float A =  (e*i - f*h), B = -(d*i - f*g), C =  (d*h - e*g);
    float inv = 1.0f / (a*A + b*B + cc*C);
    const float K0 = A*inv,  K1 = -(b*i - cc*h)*inv,  K2 =  (b*f - cc*e)*inv;
    const float K3 = B*inv,  K4 =  (a*i - cc*g)*inv,  K5 = -(a*f - cc*d)*inv;
    const float K6 = C*inv,  K7 = -(a*h - b*g)*inv,   K8 =  (a*e - b*d)*inv;

    const float L0=l[0],L1=l[1],L2=l[2],L3=l[3],L4=l[4],L5=l[5],L6=l[6],L7=l[7],L8=l[8];
    const float L9=l[9],L10=l[10],L11=l[11],L12=l[12],L13=l[13],L14=l[14];
    const float L15=l[15],L16=l[16],L17=l[17],L18=l[18],L19=l[19],L20=l[20];
    const float L21=l[21],L22=l[22],L23=l[23],L24=l[24],L25=l[25],L26=l[26];

    float acc = 0.0f;
    unsigned int cnt = 0;
    const bool emitlane = (lane >= 1) && (lane <= 30);
    const float inv9 = 1.0f / 9.0f;

    for (int s = slot; s < NSTRIPS; s += NSLOTS) {
        const int tx = s % NW_X;
        const int ty = s / NW_X;
        const int c0 = tx * TILE_W;
        const int r0 = ty * STRIP_H;
        const int col = c0 - 1 + lane;
        const bool colin  = (col >= 0) && (col < W_IMG);
        const bool colrin = (col + 1 < W_IMG);

        const float x = (float)col;
        float rx = K0 * x + K1 * (float)(r0 - 1) + K2;
        float ry = K3 * x + K4 * (float)(r0 - 1) + K5;
        float rz = K6 * x + K7 * (float)(r0 - 1) + K8;

        int off = (r0 - 1) * W_IMG + col;
        float dA = 0.0f;
        if (colin && r0 >= 1) dA = depth[off];

        float hsA0=0.f,hsA1=0.f,hsA2=0.f;
        float hsB0=0.f,hsB1=0.f,hsB2=0.f;
        float qC0=0.f,qC1=0.f,qC2=0.f;
        int   mC = 0;

        #pragma unroll 1
        for (int r = r0 - 1; r <= r0 + STRIP_H; ++r) {
            const bool rin  = ((unsigned)r < (unsigned)H_IMG);
            const bool rnin = ((unsigned)(r + 1) < (unsigned)H_IMG);

            float dB = (rnin && colin)  ? depth[off + W_IMG] : 0.0f;
            float dR = (rin  && colrin) ? depth[off + 1]     : 0.0f;
            int   m  = 0;
            float rg0 = 0.0f, rg1 = 0.0f, rg2 = 0.0f;
            if (rin && colin) {
                m = mask[off] > 0;
                int ro3 = off * 3;
                rg0 = rgb[ro3]; rg1 = rgb[ro3 + 1]; rg2 = rgb[ro3 + 2];
            }

            float b0 = 0.0f, b1 = 0.0f, b2 = 0.0f;
            if (m) {
                float px = rx * dA, py = ry * dA, pz = rz * dA;
                float axv = (rx + K0) * dR - px, ayv = (ry + K3) * dR - py, azv = (rz + K6) * dR - pz;
                float bxv = (rx + K1) * dB - px, byv = (ry + K4) * dB - py, bzv = (rz + K7) * dB - pz;
                float nx = ayv * bzv - azv * byv;
                float ny = azv * bxv - axv * bzv;
                float nz = axv * byv - ayv * bxv;
                float nn = nx*nx + ny*ny + nz*nz;
                float invn = rsqrtf(fmaxf(nn, 1e-24f));
                nx *= invn; ny *= invn; nz *= invn;
                float nx2 = nx*nx, ny2 = ny*ny, nz2 = nz*nz;
                float H1 = ny, H2 = nz, H3 = nx;
                float H4 = nx*ny, H5 = ny*nz;
                float H6 = 2.0f*nz2 - nx2 - ny2;
                float H7 = nz*nx, H8 = nx2 - ny2;
                b0 = L0 + H1*L3  + H2*L6  + H3*L9  + H4*L12 + H5*L15 + H6*L18 + H7*L21 + H8*L24;
                b1 = L1 + H1*L4  + H2*L7  + H3*L10 + H4*L13 + H5*L16 + H6*L19 + H7*L22 + H8*L25;
                b2 = L2 + H1*L5  + H2*L8  + H3*L11 + H4*L14 + H5*L17 + H6*L20 + H7*L23 + H8*L26;
            }
            float q0 = b0 - rg0, q1 = b1 - rg1, q2 = b2 - rg2;

            float ql0 = __shfl_up_sync(0xffffffffu, q0, 1), qr0 = __shfl_down_sync(0xffffffffu, q0, 1);
            float ql1 = __shfl_up_sync(0xffffffffu, q1, 1), qr1 = __shfl_down_sync(0xffffffffu, q1, 1);
            float ql2 = __shfl_up_sync(0xffffffffu, q2, 1), qr2 = __shfl_down_sync(0xffffffffu, q2, 1);
            float hs0 = ql0 + q0 + qr0;
            float hs1 = ql1 + q1 + qr1;
            float hs2 = ql2 + q2 + qr2;

            if (r > r0) {
                if (emitlane && mC) {
                    float d0 = qC0 - (hsA0 + hsB0 + hs0) * inv9;
                    float d1 = qC1 - (hsA1 + hsB1 + hs1) * inv9;
                    float d2 = qC2 - (hsA2 + hsB2 + hs2) * inv9;
                    acc += d0*d0 + d1*d1 + d2*d2;
                    cnt += 1u;
                }
            }

            hsA0 = hsB0; hsA1 = hsB1; hsA2 = hsB2;
            hsB0 = hs0;  hsB1 = hs1;  hsB2 = hs2;
            qC0 = q0; qC1 = q1; qC2 = q2; mC = m;
            dA = dB;
            off += W_IMG;
            rx += K1; ry += K4; rz += K7;
        }
    }

    // ---- reduction: warp -> block -> global ----
    #pragma unroll
    for (int o = 16; o > 0; o >>= 1) {
        acc += __shfl_down_sync(0xffffffffu, acc, o);
        cnt += __shfl_down_sync(0xffffffffu, cnt, o);
    }
    __shared__ float s_red[WPB];
    __shared__ unsigned int s_redc[WPB];
    if (lane == 0) { s_red[w] = acc; s_redc[w] = cnt; }
    __syncthreads();
    if (tid == 0) {
        float aa = 0.0f; unsigned int cn = 0;
        #pragma unroll
        for (int k = 0; k < WPB; k++) { aa += s_red[k]; cn += s_redc[k]; }
        atomicAdd(&g_num, (double)aa);
        atomicAdd(&g_cnt, cn);
        __threadfence();
        unsigned int t = atomicAdd(&g_ticket, 1u);
        if (t == NBLOCKS - 1) {
            __threadfence();
            double num = g_num;
            unsigned int c2 = g_cnt;
            out[0] = (float)(num / ((double)c2 * 3.0));
            g_num = 0.0;
            g_cnt = 0u;
            g_ticket = 0u;
        }
    }
}

extern "C" void kernel_launch(void* const* d_in, const int* in_sizes, int n_in,
                              void* d_out, int out_size) {
    const float* depth = (const float*)d_in[0];
    const float* rgb   = (const float*)d_in[1];
    const int*   mask  = (const int*)d_in[2];
    const float* l     = (const float*)d_in[3];
    const float* Kc    = (const float*)d_in[4];

    shading_loss_kernel<<<NBLOCKS, NTHREADS>>>(depth, rgb, mask, l, Kc, (float*)d_out);
}

// round 6
// speedup vs baseline: 1.1964x; 1.1964x over previous
#include <cuda_runtime.h>

#define W_IMG 3840
#define H_IMG 2160
#define TILE_W 30            // output columns per warp (lanes 1..30)
#define NW_X 128             // 3840 / 30
#define NW_Y 37              // vertical strips (58 or 59 rows each)
#define WPB 8
#define NTHREADS 256
#define NBLOCKS ((NW_X * NW_Y) / WPB)   // 4736/8 = 592 = 148 SMs x 4 blocks

__device__ double g_num;
__device__ unsigned int g_cnt;
__device__ unsigned int g_ticket;

__launch_bounds__(NTHREADS, 4)
__global__ void shading_loss_kernel(const float* __restrict__ depth,
                                    const float* __restrict__ rgb,
                                    const int*   __restrict__ mask,
                                    const float* __restrict__ l,
                                    const float* __restrict__ Kc,
                                    float* __restrict__ out)
{
    const int tid  = threadIdx.x;
    const int lane = tid & 31;
    const int w    = tid >> 5;
    const int wid  = blockIdx.x * WPB + w;
    const int tx   = wid % NW_X;
    const int ty   = wid / NW_X;
    // 2160 = 14*59 + 23*58 : first 14 strips are 59 rows tall
    const int r0   = ty * 58 + min(ty, 14);
    const int hgt  = 58 + (ty < 14 ? 1 : 0);
    const int c0   = tx * TILE_W;
    const int col  = c0 - 1 + lane;
    const bool colin  = (col >= 0) && (col < W_IMG);
    const bool colrin = (col + 1 < W_IMG);

    // camera inverse (adjugate) — uniform
    float a = Kc[0], b = Kc[1], cc = Kc[2];
    float d = Kc[3], e = Kc[4], f  = Kc[5];
    float g = Kc[6], h = Kc[7], i  = Kc[8];
    float A =  (e*i - f*h), B = -(d*i - f*g), C =  (d*h - e*g);
    float inv = 1.0f / (a*A + b*B + cc*C);
    const float K0 = A*inv,  K1 = -(b*i - cc*h)*inv,  K2 =  (b*f - cc*e)*inv;
    const float K3 = B*inv,  K4 =  (a*i - cc*g)*inv,  K5 = -(a*f - cc*d)*inv;
    const float K6 = C*inv,  K7 = -(a*h - b*g)*inv,   K8 =  (a*e - b*d)*inv;

    const float L0=l[0],L1=l[1],L2=l[2],L3=l[3],L4=l[4],L5=l[5],L6=l[6],L7=l[7],L8=l[8];
    const float L9=l[9],L10=l[10],L11=l[11],L12=l[12],L13=l[13],L14=l[14];
    const float L15=l[15],L16=l[16],L17=l[17],L18=l[18],L19=l[19],L20=l[20];
    const float L21=l[21],L22=l[22],L23=l[23],L24=l[24],L25=l[25],L26=l[26];

    // per-lane ray, updated incrementally down the column
    const float x = (float)col;
    float rx = K0 * x + K1 * (float)(r0 - 1) + K2;
    float ry = K3 * x + K4 * (float)(r0 - 1) + K5;
    float rz = K6 * x + K7 * (float)(r0 - 1) + K8;

    int off = (r0 - 1) * W_IMG + col;
    float dA = 0.0f;
    if (colin && r0 >= 1) dA = depth[off];

    float hsA0=0.f,hsA1=0.f,hsA2=0.f;
    float hsB0=0.f,hsB1=0.f,hsB2=0.f;
    float qC0=0.f,qC1=0.f,qC2=0.f;
    int   mC = 0;

    float acc = 0.0f;
    unsigned int cnt = 0;
    const bool emitlane = (lane >= 1) && (lane <= 30);
    const float inv9 = 1.0f / 9.0f;
    const int rend = r0 + hgt;

    #pragma unroll 1
    for (int r = r0 - 1; r <= rend; ++r) {
        const bool rin  = ((unsigned)r < (unsigned)H_IMG);
        const bool rnin = ((unsigned)(r + 1) < (unsigned)H_IMG);

        float dB = (rnin && colin)  ? depth[off + W_IMG] : 0.0f;
        float dR = (rin  && colrin) ? depth[off + 1]     : 0.0f;
        int   m  = 0;
        float rg0 = 0.0f, rg1 = 0.0f, rg2 = 0.0f;
        if (rin && colin) {
            m = mask[off] > 0;
            int ro3 = off * 3;
            rg0 = rgb[ro3]; rg1 = rgb[ro3 + 1]; rg2 = rgb[ro3 + 2];
        }

        float b0 = 0.0f, b1 = 0.0f, b2 = 0.0f;
        if (m) {
            float px = rx * dA, py = ry * dA, pz = rz * dA;
            float axv = (rx + K0) * dR - px, ayv = (ry + K3) * dR - py, azv = (rz + K6) * dR - pz;
            float bxv = (rx + K1) * dB - px, byv = (ry + K4) * dB - py, bzv = (rz + K7) * dB - pz;
            float nx = ayv * bzv - azv * byv;
            float ny = azv * bxv - axv * bzv;
            float nz = axv * byv - ayv * bxv;
            float nn = nx*nx + ny*ny + nz*nz;
            float invn = rsqrtf(fmaxf(nn, 1e-24f));
            nx *= invn; ny *= invn; nz *= invn;
            float nx2 = nx*nx, ny2 = ny*ny, nz2 = nz*nz;
            float H1 = ny, H2 = nz, H3 = nx;
            float H4 = nx*ny, H5 = ny*nz;
            float H6 = 2.0f*nz2 - nx2 - ny2;
            float H7 = nz*nx, H8 = nx2 - ny2;
            b0 = L0 + H1*L3  + H2*L6  + H3*L9  + H4*L12 + H5*L15 + H6*L18 + H7*L21 + H8*L24;
            b1 = L1 + H1*L4  + H2*L7  + H3*L10 + H4*L13 + H5*L16 + H6*L19 + H7*L22 + H8*L25;
            b2 = L2 + H1*L5  + H2*L8  + H3*L11 + H4*L14 + H5*L17 + H6*L20 + H7*L23 + H8*L26;
        }
        float q0 = b0 - rg0, q1 = b1 - rg1, q2 = b2 - rg2;

        float ql0 = __shfl_up_sync(0xffffffffu, q0, 1), qr0 = __shfl_down_sync(0xffffffffu, q0, 1);
        float ql1 = __shfl_up_sync(0xffffffffu, q1, 1), qr1 = __shfl_down_sync(0xffffffffu, q1, 1);
        float ql2 = __shfl_up_sync(0xffffffffu, q2, 1), qr2 = __shfl_down_sync(0xffffffffu, q2, 1);
        float hs0 = ql0 + q0 + qr0;
        float hs1 = ql1 + q1 + qr1;
        float hs2 = ql2 + q2 + qr2;

        if (r > r0) {
            if (emitlane && mC) {
                float d0 = qC0 - (hsA0 + hsB0 + hs0) * inv9;
                float d1 = qC1 - (hsA1 + hsB1 + hs1) * inv9;
                float d2 = qC2 - (hsA2 + hsB2 + hs2) * inv9;
                acc += d0*d0 + d1*d1 + d2*d2;
                cnt += 1u;
            }
        }

        hsA0 = hsB0; hsA1 = hsB1; hsA2 = hsB2;
        hsB0 = hs0;  hsB1 = hs1;  hsB2 = hs2;
        qC0 = q0; qC1 = q1; qC2 = q2; mC = m;
        dA = dB;
        off += W_IMG;
        rx += K1; ry += K4; rz += K7;
    }

    // ---- reduction: warp -> block -> global ----
    #pragma unroll
    for (int o = 16; o > 0; o >>= 1) {
        acc += __shfl_down_sync(0xffffffffu, acc, o);
        cnt += __shfl_down_sync(0xffffffffu, cnt, o);
    }
    __shared__ float s_red[WPB];
    __shared__ unsigned int s_redc[WPB];
    if (lane == 0) { s_red[w] = acc; s_redc[w] = cnt; }
    __syncthreads();
    if (tid == 0) {
        float aa = 0.0f; unsigned int cn = 0;
        #pragma unroll
        for (int k = 0; k < WPB; k++) { aa += s_red[k]; cn += s_redc[k]; }
        atomicAdd(&g_num, (double)aa);
        atomicAdd(&g_cnt, cn);
        __threadfence();
        unsigned int t = atomicAdd(&g_ticket, 1u);
        if (t == NBLOCKS - 1) {
            __threadfence();
            double num = g_num;
            unsigned int c2 = g_cnt;
            out[0] = (float)(num / ((double)c2 * 3.0));
            g_num = 0.0;
            g_cnt = 0u;
            g_ticket = 0u;
        }
    }
}

extern "C" void kernel_launch(void* const* d_in, const int* in_sizes, int n_in,
                              void* d_out, int out_size) {
    const float* depth = (const float*)d_in[0];
    const float* rgb   = (const float*)d_in[1];
    const int*   mask  = (const int*)d_in[2];
    const float* l     = (const float*)d_in[3];
    const float* Kc    = (const float*)d_in[4];

    shading_loss_kernel<<<NBLOCKS, NTHREADS>>>(depth, rgb, mask, l, Kc, (float*)d_out);
}

// round 7
// speedup vs baseline: 1.3668x; 1.1424x over previous
#include <cuda_runtime.h>

#define W_IMG 3840
#define H_IMG 2160
#define TILE_W 30            // output columns per warp (lanes 1..30)
#define NW_X 128             // 3840 / 30
#define NW_Y 37              // vertical strips (58 or 59 rows)
#define WPB 8
#define NTHREADS 256
#define NBLOCKS ((NW_X * NW_Y) / WPB)   // 592 = 148 SMs x 4 blocks

__device__ double g_num;
__device__ unsigned int g_cnt;
__device__ unsigned int g_ticket;

__launch_bounds__(NTHREADS, 4)
__global__ void shading_loss_kernel(const float* __restrict__ depth,
                                    const float* __restrict__ rgb,
                                    const int*   __restrict__ mask,
                                    const float* __restrict__ l,
                                    const float* __restrict__ Kc,
                                    float* __restrict__ out)
{
    const int tid  = threadIdx.x;
    const int lane = tid & 31;
    const int w    = tid >> 5;
    const int wid  = blockIdx.x * WPB + w;
    const int tx   = wid % NW_X;
    const int ty   = wid / NW_X;
    // 2160 = 14*59 + 23*58
    const int r0   = ty * 58 + min(ty, 14);
    const int hgt  = 58 + (ty < 14 ? 1 : 0);
    const int c0   = tx * TILE_W;
    const int col  = c0 - 1 + lane;
    const bool colin  = (col >= 0) && (col < W_IMG);
    const bool colrin = (col + 1 < W_IMG);
    const bool safe   = (tx >= 1) && (tx <= NW_X - 2) && (ty >= 1) && (ty <= NW_Y - 2);

    // camera inverse (adjugate) — uniform
    float a = Kc[0], b = Kc[1], cc = Kc[2];
    float d = Kc[3], e = Kc[4], f  = Kc[5];
    float g = Kc[6], h = Kc[7], i  = Kc[8];
    float A =  (e*i - f*h), B = -(d*i - f*g), C =  (d*h - e*g);
    float inv = 1.0f / (a*A + b*B + cc*C);
    const float K0 = A*inv,  K1 = -(b*i - cc*h)*inv,  K2 =  (b*f - cc*e)*inv;
    const float K3 = B*inv,  K4 =  (a*i - cc*g)*inv,  K5 = -(a*f - cc*d)*inv;
    const float K6 = C*inv,  K7 = -(a*h - b*g)*inv,   K8 =  (a*e - b*d)*inv;

    const float L0=l[0],L1=l[1],L2=l[2],L3=l[3],L4=l[4],L5=l[5],L6=l[6],L7=l[7],L8=l[8];
    const float L9=l[9],L10=l[10],L11=l[11],L12=l[12],L13=l[13],L14=l[14];
    const float L15=l[15],L16=l[16],L17=l[17],L18=l[18],L19=l[19],L20=l[20];
    const float L21=l[21],L22=l[22],L23=l[23],L24=l[24],L25=l[25],L26=l[26];

    const float x = (float)col;
    float rx = K0 * x + K1 * (float)(r0 - 1) + K2;
    float ry = K3 * x + K4 * (float)(r0 - 1) + K5;
    float rz = K6 * x + K7 * (float)(r0 - 1) + K8;

    float acc = 0.0f;
    unsigned int cnt = 0;
    const bool emitlane = (lane >= 1) && (lane <= 30);
    const float inv9 = 1.0f / 9.0f;
    const int rend = r0 + hgt;

    float hsA0,hsA1,hsA2, hsB0,hsB1,hsB2;
    float qC0,qC1,qC2;
    int   mC;

// Compute one row: loads + shade + horizontal 3-sum.
// Produces: q0,q1,q2 (this row's q), hs0,hs1,hs2 (horizontal sum), m (mask).
#define ROW_SAFE                                                              \
    float dB = depth[off + W_IMG];                                           \
    float dR = depth[off + 1];                                               \
    int   m  = mask[off] > 0;                                                \
    int ro3 = off * 3;                                                       \
    float rg0 = rgb[ro3], rg1 = rgb[ro3 + 1], rg2 = rgb[ro3 + 2];            \
    SHADE_BODY

#define ROW_GEN                                                               \
    const bool rin  = ((unsigned)r < (unsigned)H_IMG);                       \
    const bool rnin = ((unsigned)(r + 1) < (unsigned)H_IMG);                 \
    float dB = (rnin && colin)  ? depth[off + W_IMG] : 0.0f;                 \
    float dR = (rin  && colrin) ? depth[off + 1]     : 0.0f;                 \
    int   m  = 0;                                                            \
    float rg0 = 0.0f, rg1 = 0.0f, rg2 = 0.0f;                                \
    if (rin && colin) {                                                      \
        m = mask[off] > 0;                                                   \
        int ro3 = off * 3;                                                   \
        rg0 = rgb[ro3]; rg1 = rgb[ro3 + 1]; rg2 = rgb[ro3 + 2];              \
    }                                                                        \
    SHADE_BODY

#define SHADE_BODY                                                            \
    float b0 = 0.0f, b1 = 0.0f, b2 = 0.0f;                                   \
    if (m) {                                                                 \
        float px = rx * dA, py = ry * dA, pz = rz * dA;                      \
        float axv = (rx + K0) * dR - px, ayv = (ry + K3) * dR - py, azv = (rz + K6) * dR - pz; \
        float bxv = (rx + K1) * dB - px, byv = (ry + K4) * dB - py, bzv = (rz + K7) * dB - pz; \
        float nx = ayv * bzv - azv * byv;                                    \
        float ny = azv * bxv - axv * bzv;                                    \
        float nz = axv * byv - ayv * bxv;                                    \
        float nn = nx*nx + ny*ny + nz*nz;                                    \
        float invn = rsqrtf(fmaxf(nn, 1e-24f));                              \
        nx *= invn; ny *= invn; nz *= invn;                                  \
        float nx2 = nx*nx, ny2 = ny*ny, nz2 = nz*nz;                         \
        float H1 = ny, H2 = nz, H3 = nx;                                     \
        float H4 = nx*ny, H5 = ny*nz;                                        \
        float H6 = 2.0f*nz2 - nx2 - ny2;                                     \
        float H7 = nz*nx, H8 = nx2 - ny2;                                    \
        b0 = L0 + H1*L3  + H2*L6  + H3*L9  + H4*L12 + H5*L15 + H6*L18 + H7*L21 + H8*L24; \
        b1 = L1 + H1*L4  + H2*L7  + H3*L10 + H4*L13 + H5*L16 + H6*L19 + H7*L22 + H8*L25; \
        b2 = L2 + H1*L5  + H2*L8  + H3*L11 + H4*L14 + H5*L17 + H6*L20 + H7*L23 + H8*L26; \
    }                                                                        \
    float q0 = b0 - rg0, q1 = b1 - rg1, q2 = b2 - rg2;                       \
    float hs0, hs1, hs2;                                                     \
    {                                                                        \
        float ql0 = __shfl_up_sync(0xffffffffu, q0, 1), qr0 = __shfl_down_sync(0xffffffffu, q0, 1); \
        float ql1 = __shfl_up_sync(0xffffffffu, q1, 1), qr1 = __shfl_down_sync(0xffffffffu, q1, 1); \
        float ql2 = __shfl_up_sync(0xffffffffu, q2, 1), qr2 = __shfl_down_sync(0xffffffffu, q2, 1); \
        hs0 = ql0 + q0 + qr0;                                                \
        hs1 = ql1 + q1 + qr1;                                                \
        hs2 = ql2 + q2 + qr2;                                                \
    }                                                                        \
    dA = dB;                                                                 \
    off += W_IMG;                                                            \
    rx += K1; ry += K4; rz += K7;

#define EMIT                                                                  \
    if (emitlane && mC) {                                                    \
        float d0 = qC0 - (hsA0 + hsB0 + hs0) * inv9;                         \
        float d1 = qC1 - (hsA1 + hsB1 + hs1) * inv9;                         \
        float d2 = qC2 - (hsA2 + hsB2 + hs2) * inv9;                         \
        acc += d0*d0 + d1*d1 + d2*d2;                                        \
        cnt += 1u;                                                           \
    }

#define ROTATE                                                                \
    hsA0 = hsB0; hsA1 = hsB1; hsA2 = hsB2;                                   \
    hsB0 = hs0;  hsB1 = hs1;  hsB2 = hs2;                                    \
    qC0 = q0; qC1 = q1; qC2 = q2; mC = m;

    if (safe) {
        int off = (r0 - 1) * W_IMG + col;
        float dA = depth[off];
        // warm-up row r0-1 -> hsA
        { ROW_SAFE; hsA0 = hs0; hsA1 = hs1; hsA2 = hs2; (void)m; }
        // warm-up row r0 -> hsB, qC
        { ROW_SAFE; hsB0 = hs0; hsB1 = hs1; hsB2 = hs2;
          qC0 = q0; qC1 = q1; qC2 = q2; mC = m; }
        // steady rows r0+1 .. rend: emit row r-1 each iteration
        #pragma unroll 2
        for (int r = r0 + 1; r <= rend; ++r) {
            ROW_SAFE;
            EMIT;
            ROTATE;
        }
    } else {
        int off = (r0 - 1) * W_IMG + col;
        float dA = 0.0f;
        if (colin && r0 >= 1) dA = depth[off];
        { int r = r0 - 1; ROW_GEN; hsA0 = hs0; hsA1 = hs1; hsA2 = hs2; (void)m; }
        { int r = r0;     ROW_GEN; hsB0 = hs0; hsB1 = hs1; hsB2 = hs2;
          qC0 = q0; qC1 = q1; qC2 = q2; mC = m; }
        #pragma unroll 1
        for (int r = r0 + 1; r <= rend; ++r) {
            ROW_GEN;
            EMIT;
            ROTATE;
        }
    }

    // ---- reduction: warp -> block -> global ----
    #pragma unroll
    for (int o = 16; o > 0; o >>= 1) {
        acc += __shfl_down_sync(0xffffffffu, acc, o);
        cnt += __shfl_down_sync(0xffffffffu, cnt, o);
    }
    __shared__ float s_red[WPB];
    __shared__ unsigned int s_redc[WPB];
    if (lane == 0) { s_red[w] = acc; s_redc[w] = cnt; }
    __syncthreads();
    if (tid == 0) {
        float aa = 0.0f; unsigned int cn = 0;
        #pragma unroll
        for (int k = 0; k < WPB; k++) { aa += s_red[k]; cn += s_redc[k]; }
        atomicAdd(&g_num, (double)aa);
        atomicAdd(&g_cnt, cn);
        __threadfence();
        unsigned int t = atomicAdd(&g_ticket, 1u);
        if (t == NBLOCKS - 1) {
            __threadfence();
            double num = g_num;
            unsigned int c2 = g_cnt;
            out[0] = (float)(num / ((double)c2 * 3.0));
            g_num = 0.0;
            g_cnt = 0u;
            g_ticket = 0u;
        }
    }
}

extern "C" void kernel_launch(void* const* d_in, const int* in_sizes, int n_in,
                              void* d_out, int out_size) {
    const float* depth = (const float*)d_in[0];
    const float* rgb   = (const float*)d_in[1];
    const int*   mask  = (const int*)d_in[2];
    const float* l     = (const float*)d_in[3];
    const float* Kc    = (const float*)d_in[4];

    shading_loss_kernel<<<NBLOCKS, NTHREADS>>>(depth, rgb, mask, l, Kc, (float*)d_out);
}

// round 8
// speedup vs baseline: 1.4112x; 1.0325x over previous
#include <cuda_runtime.h>

#define W_IMG 3840
#define H_IMG 2160
#define TILE_W 30            // output columns per warp (lanes 1..30)
#define NW_X 128             // 3840 / 30
#define NW_Y 46              // vertical strips (47 or 46 rows)
#define WPB 8
#define NTHREADS 256
#define NBLOCKS ((NW_X * NW_Y) / WPB)   // 5888/8 = 736 blocks -> 5 per SM (mostly)

__device__ double g_num;
__device__ unsigned int g_cnt;
__device__ unsigned int g_ticket;

__constant__ float c_l[27];
__constant__ float c_Kc[9];

__launch_bounds__(NTHREADS, 5)
__global__ void shading_loss_kernel(const float* __restrict__ depth,
                                    const float* __restrict__ rgb,
                                    const int*   __restrict__ mask,
                                    float* __restrict__ out)
{
    const int tid  = threadIdx.x;
    const int lane = tid & 31;
    const int w    = tid >> 5;
    const int wid  = blockIdx.x * WPB + w;
    const int tx   = wid % NW_X;
    const int ty   = wid / NW_X;
    // 2160 = 44*47 + 2*46 : first 44 strips are 47 rows tall
    const int r0   = ty * 46 + min(ty, 44);
    const int hgt  = 46 + (ty < 44 ? 1 : 0);
    const int c0   = tx * TILE_W;
    const int col  = c0 - 1 + lane;
    const bool colin  = (col >= 0) && (col < W_IMG);
    const bool colrin = (col + 1 < W_IMG);
    const bool safe   = (tx >= 1) && (tx <= NW_X - 2) && (ty >= 1) && (ty <= NW_Y - 2);

    // camera inverse (adjugate) from constant bank — uniform arithmetic
    float a = c_Kc[0], b = c_Kc[1], cc = c_Kc[2];
    float d = c_Kc[3], e = c_Kc[4], f  = c_Kc[5];
    float g = c_Kc[6], h = c_Kc[7], i  = c_Kc[8];
    float A =  (e*i - f*h), B = -(d*i - f*g), C =  (d*h - e*g);
    float inv = 1.0f / (a*A + b*B + cc*C);
    const float K0 = A*inv,  K1 = -(b*i - cc*h)*inv,  K2 =  (b*f - cc*e)*inv;
    const float K3 = B*inv,  K4 =  (a*i - cc*g)*inv,  K5 = -(a*f - cc*d)*inv;
    const float K6 = C*inv,  K7 = -(a*h - b*g)*inv,   K8 =  (a*e - b*d)*inv;

    const float x = (float)col;
    float rx = K0 * x + K1 * (float)(r0 - 1) + K2;
    float ry = K3 * x + K4 * (float)(r0 - 1) + K5;
    float rz = K6 * x + K7 * (float)(r0 - 1) + K8;

    float acc = 0.0f;
    unsigned int cnt = 0;
    const bool emitlane = (lane >= 1) && (lane <= 30);
    const float inv9 = 1.0f / 9.0f;
    const int rend = r0 + hgt;

    float hsA0,hsA1,hsA2, hsB0,hsB1,hsB2;
    float qC0,qC1,qC2;
    int   mC;

#define ROW_SAFE                                                              \
    float dB = depth[off + W_IMG];                                           \
    float dR = depth[off + 1];                                               \
    int   m  = mask[off] > 0;                                                \
    int ro3 = off * 3;                                                       \
    float rg0 = rgb[ro3], rg1 = rgb[ro3 + 1], rg2 = rgb[ro3 + 2];            \
    SHADE_BODY

#define ROW_GEN                                                               \
    const bool rin  = ((unsigned)r < (unsigned)H_IMG);                       \
    const bool rnin = ((unsigned)(r + 1) < (unsigned)H_IMG);                 \
    float dB = (rnin && colin)  ? depth[off + W_IMG] : 0.0f;                 \
    float dR = (rin  && colrin) ? depth[off + 1]     : 0.0f;                 \
    int   m  = 0;                                                            \
    float rg0 = 0.0f, rg1 = 0.0f, rg2 = 0.0f;                                \
    if (rin && colin) {                                                      \
        m = mask[off] > 0;                                                   \
        int ro3 = off * 3;                                                   \
        rg0 = rgb[ro3]; rg1 = rgb[ro3 + 1]; rg2 = rgb[ro3 + 2];              \
    }                                                                        \
    SHADE_BODY

#define SHADE_BODY                                                            \
    float b0 = 0.0f, b1 = 0.0f, b2 = 0.0f;                                   \
    if (m) {                                                                 \
        float px = rx * dA, py = ry * dA, pz = rz * dA;                      \
        float axv = (rx + K0) * dR - px, ayv = (ry + K3) * dR - py, azv = (rz + K6) * dR - pz; \
        float bxv = (rx + K1) * dB - px, byv = (ry + K4) * dB - py, bzv = (rz + K7) * dB - pz; \
        float nx = ayv * bzv - azv * byv;                                    \
        float ny = azv * bxv - axv * bzv;                                    \
        float nz = axv * byv - ayv * bxv;                                    \
        float nn = nx*nx + ny*ny + nz*nz;                                    \
        float invn = rsqrtf(fmaxf(nn, 1e-24f));                              \
        nx *= invn; ny *= invn; nz *= invn;                                  \
        float nx2 = nx*nx, ny2 = ny*ny, nz2 = nz*nz;                         \
        float H1 = ny, H2 = nz, H3 = nx;                                     \
        float H4 = nx*ny, H5 = ny*nz;                                        \
        float H6 = 2.0f*nz2 - nx2 - ny2;                                     \
        float H7 = nz*nx, H8 = nx2 - ny2;                                    \
        b0 = c_l[0] + H1*c_l[3]  + H2*c_l[6]  + H3*c_l[9]  + H4*c_l[12] + H5*c_l[15] + H6*c_l[18] + H7*c_l[21] + H8*c_l[24]; \
        b1 = c_l[1] + H1*c_l[4]  + H2*c_l[7]  + H3*c_l[10] + H4*c_l[13] + H5*c_l[16] + H6*c_l[19] + H7*c_l[22] + H8*c_l[25]; \
        b2 = c_l[2] + H1*c_l[5]  + H2*c_l[8]  + H3*c_l[11] + H4*c_l[14] + H5*c_l[17] + H6*c_l[20] + H7*c_l[23] + H8*c_l[26]; \
    }                                                                        \
    float q0 = b0 - rg0, q1 = b1 - rg1, q2 = b2 - rg2;                       \
    float hs0, hs1, hs2;                                                     \
    {                                                                        \
        float ql0 = __shfl_up_sync(0xffffffffu, q0, 1), qr0 = __shfl_down_sync(0xffffffffu, q0, 1); \
        float ql1 = __shfl_up_sync(0xffffffffu, q1, 1), qr1 = __shfl_down_sync(0xffffffffu, q1, 1); \
        float ql2 = __shfl_up_sync(0xffffffffu, q2, 1), qr2 = __shfl_down_sync(0xffffffffu, q2, 1); \
        hs0 = ql0 + q0 + qr0;                                                \
        hs1 = ql1 + q1 + qr1;                                                \
        hs2 = ql2 + q2 + qr2;                                                \
    }                                                                        \
    dA = dB;                                                                 \
    off += W_IMG;                                                            \
    rx += K1; ry += K4; rz += K7;

#define EMIT                                                                  \
    if (emitlane && mC) {                                                    \
        float d0 = qC0 - (hsA0 + hsB0 + hs0) * inv9;                         \
        float d1 = qC1 - (hsA1 + hsB1 + hs1) * inv9;                         \
        float d2 = qC2 - (hsA2 + hsB2 + hs2) * inv9;                         \
        acc += d0*d0 + d1*d1 + d2*d2;                                        \
        cnt += 1u;                                                           \
    }

#define ROTATE                                                                \
    hsA0 = hsB0; hsA1 = hsB1; hsA2 = hsB2;                                   \
    hsB0 = hs0;  hsB1 = hs1;  hsB2 = hs2;                                    \
    qC0 = q0; qC1 = q1; qC2 = q2; mC = m;

    if (safe) {
        int off = (r0 - 1) * W_IMG + col;
        float dA = depth[off];
        { ROW_SAFE; hsA0 = hs0; hsA1 = hs1; hsA2 = hs2; (void)m; }
        { ROW_SAFE; hsB0 = hs0; hsB1 = hs1; hsB2 = hs2;
          qC0 = q0; qC1 = q1; qC2 = q2; mC = m; }
        #pragma unroll 2
        for (int r = r0 + 1; r <= rend; ++r) {
            ROW_SAFE;
            EMIT;
            ROTATE;
        }
    } else {
        int off = (r0 - 1) * W_IMG + col;
        float dA = 0.0f;
        if (colin && r0 >= 1) dA = depth[off];
        { int r = r0 - 1; ROW_GEN; hsA0 = hs0; hsA1 = hs1; hsA2 = hs2; (void)m; }
        { int r = r0;     ROW_GEN; hsB0 = hs0; hsB1 = hs1; hsB2 = hs2;
          qC0 = q0; qC1 = q1; qC2 = q2; mC = m; }
        #pragma unroll 1
        for (int r = r0 + 1; r <= rend; ++r) {
            ROW_GEN;
            EMIT;
            ROTATE;
        }
    }

    // ---- reduction: warp -> block -> global ----
    #pragma unroll
    for (int o = 16; o > 0; o >>= 1) {
        acc += __shfl_down_sync(0xffffffffu, acc, o);
        cnt += __shfl_down_sync(0xffffffffu, cnt, o);
    }
    __shared__ float s_red[WPB];
    __shared__ unsigned int s_redc[WPB];
    if (lane == 0) { s_red[w] = acc; s_redc[w] = cnt; }
    __syncthreads();
    if (tid == 0) {
        float aa = 0.0f; unsigned int cn = 0;
        #pragma unroll
        for (int k = 0; k < WPB; k++) { aa += s_red[k]; cn += s_redc[k]; }
        atomicAdd(&g_num, (double)aa);
        atomicAdd(&g_cnt, cn);
        __threadfence();
        unsigned int t = atomicAdd(&g_ticket, 1u);
        if (t == NBLOCKS - 1) {
            __threadfence();
            double num = g_num;
            unsigned int c2 = g_cnt;
            out[0] = (float)(num / ((double)c2 * 3.0));
            g_num = 0.0;
            g_cnt = 0u;
            g_ticket = 0u;
        }
    }
}

extern "C" void kernel_launch(void* const* d_in, const int* in_sizes, int n_in,
                              void* d_out, int out_size) {
    const float* depth = (const float*)d_in[0];
    const float* rgb   = (const float*)d_in[1];
    const int*   mask  = (const int*)d_in[2];
    const float* l     = (const float*)d_in[3];
    const float* Kc    = (const float*)d_in[4];

    // Stage uniform coefficients into the constant bank (graph-capturable D2D copies)
    cudaMemcpyToSymbolAsync(c_l,  l,  27 * sizeof(float), 0, cudaMemcpyDeviceToDevice);
    cudaMemcpyToSymbolAsync(c_Kc, Kc,  9 * sizeof(float), 0, cudaMemcpyDeviceToDevice);

    shading_loss_kernel<<<NBLOCKS, NTHREADS>>>(depth, rgb, mask, (float*)d_out);
}